// round 3
// baseline (speedup 1.0000x reference)
#include <cuda_runtime.h>

#define N0MAX 500000
#define EPS 1e-4f

// ---------------------------------------------------------------------------
// Scratch (device globals — no runtime allocation allowed)
// ---------------------------------------------------------------------------
__device__ float g_X0[N0MAX * 16];
__device__ float g_X1[N0MAX * 16];
__device__ float g_X2[N0MAX * 16];
__device__ float g_T1[N0MAX * 16];
__device__ float g_T2[N0MAX * 16];
// pair buffers: 3 rulebooks of K=27 + 2 of K=8, bucket stride N0MAX
__device__ int2     g_pairs[(size_t)97 * N0MAX];
__device__ int      g_cnt[5 * 32];
__device__ float    g_stats[96];   // sum[0..47], sumsq[48..95]
__device__ float    g_scale[48];
__device__ float    g_shift[48];
__device__ unsigned g_ticket;

// rulebook bucket-base offsets into g_pairs / g_cnt
#define RB0_P ((size_t)0)
#define RB1_P ((size_t)27 * N0MAX)
#define RB2_P ((size_t)54 * N0MAX)
#define RB3_P ((size_t)81 * N0MAX)
#define RB4_P ((size_t)89 * N0MAX)

// ---------------------------------------------------------------------------
// f32x2 packed-math helpers (sm_103a FFMA2 — only reachable via PTX)
// ---------------------------------------------------------------------------
__device__ __forceinline__ unsigned long long fma2(unsigned long long a,
                                                   unsigned long long b,
                                                   unsigned long long c) {
    unsigned long long d;
    asm("fma.rn.f32x2 %0, %1, %2, %3;" : "=l"(d) : "l"(a), "l"(b), "l"(c));
    return d;
}
__device__ __forceinline__ unsigned long long dup2(float v) {
    unsigned long long d;
    asm("mov.b64 %0, {%1, %1};" : "=l"(d) : "f"(v));
    return d;
}
__device__ __forceinline__ float2 up2(unsigned long long v) {
    float2 f;
    asm("mov.b64 {%0, %1}, %2;" : "=f"(f.x), "=f"(f.y) : "l"(v));
    return f;
}
__device__ __forceinline__ void red4(float* p, float4 v) {
    asm volatile("red.global.add.v4.f32 [%0], {%1, %2, %3, %4};"
                 :: "l"(p), "f"(v.x), "f"(v.y), "f"(v.z), "f"(v.w) : "memory");
}

// ---------------------------------------------------------------------------
// Zero counters + stats (start of every call)
// ---------------------------------------------------------------------------
__global__ void zero_misc_kernel() {
    int t = threadIdx.x;
    if (t < 160) g_cnt[t] = 0;
    if (t < 96) g_stats[t] = 0.0f;
    if (t == 0) g_ticket = 0u;
}

// ---------------------------------------------------------------------------
// Rulebook compaction (single-phase, lean): per-warp ballot + one global
// atomic per (warp,k), immediate pair write. Low regs -> high occupancy.
// ---------------------------------------------------------------------------
template <int K>
__global__ void compact_kernel(const int* __restrict__ nbr, int Nout, int Nin,
                               int cbase, size_t pbase) {
    int i = blockIdx.x * blockDim.x + threadIdx.x;
    bool inb = i < Nout;
    int lane = threadIdx.x & 31;
    unsigned lt = (1u << lane) - 1u;
#pragma unroll 1
    for (int k = 0; k < K; k++) {
        int idx = inb ? __ldg(nbr + (size_t)k * Nout + i) : Nin;
        bool act = idx < Nin;
        unsigned m = __ballot_sync(0xffffffffu, act);
        if (!m) continue;
        int base = 0;
        if (lane == 0) base = atomicAdd(&g_cnt[cbase + k], __popc(m));
        base = __shfl_sync(0xffffffffu, base, 0);
        if (act)
            g_pairs[pbase + (size_t)k * N0MAX + base + __popc(m & lt)] =
                make_int2(i, idx);
    }
}

// ---------------------------------------------------------------------------
// Pair-parallel sparse conv, 16->16, f32x2 packed math.
// One thread = one (out_i, in_idx, k) pair; k warp-uniform (k-major buckets)
// -> broadcast LDS.128 weight reads. Accumulate via red.global.add.v4.f32.
// Bucket prefix computed per-block from g_cnt (no separate scan kernel).
// ---------------------------------------------------------------------------
template <int K>
__global__ void pairconv16_kernel(size_t pbase, int cbase,
                                  const float* __restrict__ y,
                                  const float* __restrict__ Wg,  // [K,16,16]
                                  float* __restrict__ out) {
    __shared__ float4 Ws[K * 64];
    __shared__ int spfx[K + 1];
    for (int t = threadIdx.x; t < K * 64; t += blockDim.x)
        Ws[t] = __ldg((const float4*)Wg + t);
    if (threadIdx.x == 0) {
        int s = 0;
        for (int k = 0; k < K; k++) { spfx[k] = s; s += g_cnt[cbase + k]; }
        spfx[K] = s;
    }
    __syncthreads();
    int P = spfx[K];

    for (int t = blockIdx.x * blockDim.x + threadIdx.x; t < P;
         t += gridDim.x * blockDim.x) {
        int lo = 0, hi = K;
        while (hi - lo > 1) {
            int mid = (lo + hi) >> 1;
            if (spfx[mid] <= t) lo = mid; else hi = mid;
        }
        int2 pr = __ldg(&g_pairs[pbase + (size_t)lo * N0MAX + (t - spfx[lo])]);
        const float4* yr = (const float4*)(y + (size_t)pr.y * 16);
        float4 y0 = __ldg(yr + 0), y1 = __ldg(yr + 1);
        float4 y2 = __ldg(yr + 2), y3 = __ldg(yr + 3);
        const ulonglong2* Wk = (const ulonglong2*)(Ws + (size_t)lo * 64);
        unsigned long long a0 = 0, a1 = 0, a2 = 0, a3 = 0,
                           a4 = 0, a5 = 0, a6 = 0, a7 = 0;

#define JSTEP(jj, yv) { \
        unsigned long long yy = dup2(yv); \
        ulonglong2 p0 = Wk[4*(jj)+0], p1 = Wk[4*(jj)+1]; \
        ulonglong2 p2 = Wk[4*(jj)+2], p3 = Wk[4*(jj)+3]; \
        a0 = fma2(yy, p0.x, a0); a1 = fma2(yy, p0.y, a1); \
        a2 = fma2(yy, p1.x, a2); a3 = fma2(yy, p1.y, a3); \
        a4 = fma2(yy, p2.x, a4); a5 = fma2(yy, p2.y, a5); \
        a6 = fma2(yy, p3.x, a6); a7 = fma2(yy, p3.y, a7); }

        JSTEP(0, y0.x)  JSTEP(1, y0.y)  JSTEP(2, y0.z)  JSTEP(3, y0.w)
        JSTEP(4, y1.x)  JSTEP(5, y1.y)  JSTEP(6, y1.z)  JSTEP(7, y1.w)
        JSTEP(8, y2.x)  JSTEP(9, y2.y)  JSTEP(10, y2.z) JSTEP(11, y2.w)
        JSTEP(12, y3.x) JSTEP(13, y3.y) JSTEP(14, y3.z) JSTEP(15, y3.w)
#undef JSTEP

        float* op = out + (size_t)pr.x * 16;
        float2 f0 = up2(a0), f1 = up2(a1), f2 = up2(a2), f3 = up2(a3);
        float2 f4 = up2(a4), f5 = up2(a5), f6 = up2(a6), f7 = up2(a7);
        red4(op + 0,  make_float4(f0.x, f0.y, f1.x, f1.y));
        red4(op + 4,  make_float4(f2.x, f2.y, f3.x, f3.y));
        red4(op + 8,  make_float4(f4.x, f4.y, f5.x, f5.y));
        red4(op + 12, make_float4(f6.x, f6.y, f7.x, f7.y));
    }
}

// p1 pair conv: Cin=2 -> 16, K=27, input = raw feats (no BN)
__global__ void pairconv_p1_kernel(const float* __restrict__ feats,
                                   const float* __restrict__ Wg,  // [27,2,16]
                                   float* __restrict__ out) {
    __shared__ float4 Ws[27 * 8];
    __shared__ int spfx[28];
    for (int t = threadIdx.x; t < 27 * 8; t += blockDim.x)
        Ws[t] = __ldg((const float4*)Wg + t);
    if (threadIdx.x == 0) {
        int s = 0;
        for (int k = 0; k < 27; k++) { spfx[k] = s; s += g_cnt[k]; }
        spfx[27] = s;
    }
    __syncthreads();
    int P = spfx[27];

    for (int t = blockIdx.x * blockDim.x + threadIdx.x; t < P;
         t += gridDim.x * blockDim.x) {
        int lo = 0, hi = 27;
        while (hi - lo > 1) {
            int mid = (lo + hi) >> 1;
            if (spfx[mid] <= t) lo = mid; else hi = mid;
        }
        int2 pr = __ldg(&g_pairs[RB0_P + (size_t)lo * N0MAX + (t - spfx[lo])]);
        float2 f = __ldg((const float2*)(feats + (size_t)pr.y * 2));
        const float4* Wk = &Ws[lo * 8];
        float4 u0 = Wk[0], u1 = Wk[1], u2 = Wk[2], u3 = Wk[3];
        float4 v0 = Wk[4], v1 = Wk[5], v2 = Wk[6], v3 = Wk[7];
        float4 a0 = make_float4(fmaf(f.y, v0.x, f.x * u0.x), fmaf(f.y, v0.y, f.x * u0.y),
                                fmaf(f.y, v0.z, f.x * u0.z), fmaf(f.y, v0.w, f.x * u0.w));
        float4 a1 = make_float4(fmaf(f.y, v1.x, f.x * u1.x), fmaf(f.y, v1.y, f.x * u1.y),
                                fmaf(f.y, v1.z, f.x * u1.z), fmaf(f.y, v1.w, f.x * u1.w));
        float4 a2 = make_float4(fmaf(f.y, v2.x, f.x * u2.x), fmaf(f.y, v2.y, f.x * u2.y),
                                fmaf(f.y, v2.z, f.x * u2.z), fmaf(f.y, v2.w, f.x * u2.w));
        float4 a3 = make_float4(fmaf(f.y, v3.x, f.x * u3.x), fmaf(f.y, v3.y, f.x * u3.y),
                                fmaf(f.y, v3.z, f.x * u3.z), fmaf(f.y, v3.w, f.x * u3.w));
        float* op = out + (size_t)pr.x * 16;
        red4(op + 0, a0); red4(op + 4, a1); red4(op + 8, a2); red4(op + 12, a3);
    }
}

// ---------------------------------------------------------------------------
// y = relu(x*scale+shift); optionally zero-init zb[Nz rows] in the same pass.
// ---------------------------------------------------------------------------
__global__ void bnrelu_zero_kernel(const float* __restrict__ x,
                                   float* __restrict__ y,
                                   float* __restrict__ zb, int N, int Nz) {
    int i = blockIdx.x * blockDim.x + threadIdx.x;
    if (i < N) {
        const float4* xr = (const float4*)(x + (size_t)i * 16);
        float4* yr = (float4*)(y + (size_t)i * 16);
#pragma unroll
        for (int q = 0; q < 4; q++) {
            float4 v = __ldg(xr + q);
            v.x = fmaxf(fmaf(v.x, g_scale[4 * q + 0], g_shift[4 * q + 0]), 0.f);
            v.y = fmaxf(fmaf(v.y, g_scale[4 * q + 1], g_shift[4 * q + 1]), 0.f);
            v.z = fmaxf(fmaf(v.z, g_scale[4 * q + 2], g_shift[4 * q + 2]), 0.f);
            v.w = fmaxf(fmaf(v.w, g_scale[4 * q + 3], g_shift[4 * q + 3]), 0.f);
            yr[q] = v;
        }
    }
    if (zb != nullptr && i < Nz) {
        float4* zr = (float4*)(zb + (size_t)i * 16);
        float4 z = make_float4(0.f, 0.f, 0.f, 0.f);
        zr[0] = z; zr[1] = z; zr[2] = z; zr[3] = z;
    }
}

// ---------------------------------------------------------------------------
// Per-channel sum / sumsq over N rows (optional gather row=pB[pA[i]]), with
// BN finalize fused into the last-arriving block (Cfin>0).
// ---------------------------------------------------------------------------
__global__ void reduce16_kernel(const float* __restrict__ x,
                                const int* __restrict__ pA,
                                const int* __restrict__ pB,
                                int N, int off,
                                const float* __restrict__ gg,
                                const float* __restrict__ bb,
                                float invN, int Cfin) {
    float s[16], q[16];
#pragma unroll
    for (int c = 0; c < 16; c++) { s[c] = 0.0f; q[c] = 0.0f; }

    for (int i = blockIdx.x * blockDim.x + threadIdx.x; i < N;
         i += gridDim.x * blockDim.x) {
        int r = i;
        if (pA) r = __ldg(pA + r);
        if (pB) r = __ldg(pB + r);
        const float4* xr = (const float4*)(x + (size_t)r * 16);
#pragma unroll
        for (int t = 0; t < 4; t++) {
            float4 v = __ldg(xr + t);
            s[4 * t + 0] += v.x; q[4 * t + 0] += v.x * v.x;
            s[4 * t + 1] += v.y; q[4 * t + 1] += v.y * v.y;
            s[4 * t + 2] += v.z; q[4 * t + 2] += v.z * v.z;
            s[4 * t + 3] += v.w; q[4 * t + 3] += v.w * v.w;
        }
    }
#pragma unroll
    for (int c = 0; c < 16; c++) {
#pragma unroll
        for (int o = 16; o > 0; o >>= 1) {
            s[c] += __shfl_xor_sync(0xffffffffu, s[c], o);
            q[c] += __shfl_xor_sync(0xffffffffu, q[c], o);
        }
    }
    __shared__ float ws[8][32];
    __shared__ bool last;
    int lane = threadIdx.x & 31, wid = threadIdx.x >> 5;
    if (lane == 0) {
#pragma unroll
        for (int c = 0; c < 16; c++) { ws[wid][c] = s[c]; ws[wid][16 + c] = q[c]; }
    }
    __syncthreads();
    if (threadIdx.x < 32) {
        float v = 0.0f;
        int nw = blockDim.x >> 5;
        for (int w = 0; w < nw; w++) v += ws[w][threadIdx.x];
        int t = threadIdx.x;
        int gi = (t < 16) ? (off + t) : (48 + off + (t - 16));
        atomicAdd(&g_stats[gi], v);
    }
    if (Cfin == 0) return;
    __threadfence();
    if (threadIdx.x == 0) {
        unsigned tk = atomicAdd(&g_ticket, 1u);
        last = (tk == (unsigned)gridDim.x - 1u);
    }
    __syncthreads();
    if (!last) return;
    if (threadIdx.x == 0) g_ticket = 0u;
    int t = threadIdx.x;
    if (t < Cfin) {
        float sm = __ldcg(&g_stats[t]);
        float sq = __ldcg(&g_stats[48 + t]);
        float m = sm * invN;
        float var = sq * invN - m * m;
        float sc = __ldg(gg + t) * rsqrtf(var + EPS);
        g_scale[t] = sc;
        g_shift[t] = __ldg(bb + t) - m * sc;
        g_stats[t] = 0.0f;
        g_stats[48 + t] = 0.0f;
    }
}

// ---------------------------------------------------------------------------
// Final: fused unpool-join (3x16 gather) + BN3-ReLU + SDF linear head.
// ---------------------------------------------------------------------------
__global__ void final_out_kernel(const float* __restrict__ x0,
                                 const float* __restrict__ x1,
                                 const float* __restrict__ x2,
                                 const int* __restrict__ p01,
                                 const int* __restrict__ p12,
                                 const float* __restrict__ wsdf,
                                 const float* __restrict__ bsdf,
                                 float* __restrict__ out, int N0) {
    __shared__ float sw[48], ssc[48], ssh[48];
    if (threadIdx.x < 48) {
        sw[threadIdx.x] = __ldg(wsdf + threadIdx.x);
        ssc[threadIdx.x] = g_scale[threadIdx.x];
        ssh[threadIdx.x] = g_shift[threadIdx.x];
    }
    __syncthreads();
    int i = blockIdx.x * blockDim.x + threadIdx.x;
    if (i >= N0) return;
    int p = __ldg(p01 + i);
    int qq = __ldg(p12 + p);
    float r = __ldg(bsdf);
    const float* rows[3] = { x0 + (size_t)i * 16, x1 + (size_t)p * 16,
                             x2 + (size_t)qq * 16 };
#pragma unroll
    for (int gidx = 0; gidx < 3; gidx++) {
        const float4* xr = (const float4*)rows[gidx];
#pragma unroll
        for (int t = 0; t < 4; t++) {
            float4 v = __ldg(xr + t);
            int c = gidx * 16 + t * 4;
            r += fmaxf(fmaf(v.x, ssc[c + 0], ssh[c + 0]), 0.0f) * sw[c + 0];
            r += fmaxf(fmaf(v.y, ssc[c + 1], ssh[c + 1]), 0.0f) * sw[c + 1];
            r += fmaxf(fmaf(v.z, ssc[c + 2], ssh[c + 2]), 0.0f) * sw[c + 2];
            r += fmaxf(fmaf(v.w, ssc[c + 3], ssh[c + 3]), 0.0f) * sw[c + 3];
        }
    }
    out[i] = r;
}

// ---------------------------------------------------------------------------
// Host orchestration
// ---------------------------------------------------------------------------
static inline int gdiv(int n, int t) { return (n + t - 1) / t; }

extern "C" void kernel_launch(void* const* d_in, const int* in_sizes, int n_in,
                              void* d_out, int out_size) {
    const float* feats = (const float*)d_in[0];
    const float* w_p1  = (const float*)d_in[1];
    const float* bn1g  = (const float*)d_in[2];
    const float* bn1b  = (const float*)d_in[3];
    const float* w1    = (const float*)d_in[4];
    const float* bn2g  = (const float*)d_in[5];
    const float* bn2b  = (const float*)d_in[6];
    const float* w2    = (const float*)d_in[7];
    const float* dbng  = (const float*)d_in[8];
    const float* dbnb  = (const float*)d_in[9];
    const float* dw    = (const float*)d_in[10];
    const float* bn3g  = (const float*)d_in[11];
    const float* bn3b  = (const float*)d_in[12];
    const float* wsdf  = (const float*)d_in[13];
    const float* bsdf  = (const float*)d_in[14];
    const int* nbr0    = (const int*)d_in[15];
    const int* nbr1    = (const int*)d_in[16];
    const int* nbr2    = (const int*)d_in[17];
    const int* down01  = (const int*)d_in[18];
    const int* down12  = (const int*)d_in[19];
    const int* p01     = (const int*)d_in[20];
    const int* p12     = (const int*)d_in[21];

    int N0 = in_sizes[0] / 2;
    int N1 = in_sizes[16] / 27;
    int N2 = in_sizes[17] / 27;

    float *X0, *X1, *X2, *T1, *T2;
    cudaGetSymbolAddress((void**)&X0, g_X0);
    cudaGetSymbolAddress((void**)&X1, g_X1);
    cudaGetSymbolAddress((void**)&X2, g_X2);
    cudaGetSymbolAddress((void**)&T1, g_T1);
    cudaGetSymbolAddress((void**)&T2, g_T2);

    const int T = 256;
    const int PG = 1184;   // grid-stride grid for pair convs
    const int RG0 = (gdiv(N0, T) < 1184) ? gdiv(N0, T) : 1184;
    const int RG1 = (gdiv(N1, T) < 1184) ? gdiv(N1, T) : 1184;
    const int RG2 = (gdiv(N2, T) < 1184) ? gdiv(N2, T) : 1184;

    // ---- compaction of all 5 rulebooks ----
    zero_misc_kernel<<<1, 256>>>();
    compact_kernel<27><<<gdiv(N0, T), T>>>(nbr0, N0, N0, 0,    RB0_P);
    compact_kernel<27><<<gdiv(N1, T), T>>>(nbr1, N1, N1, 32,   RB1_P);
    compact_kernel<27><<<gdiv(N2, T), T>>>(nbr2, N2, N2, 64,   RB2_P);
    compact_kernel<8> <<<gdiv(N1, T), T>>>(down01, N1, N0, 96,  RB3_P);
    compact_kernel<8> <<<gdiv(N2, T), T>>>(down12, N2, N1, 128, RB4_P);

    // ---- level 0 ----
    cudaMemsetAsync(X0, 0, (size_t)N0 * 16 * sizeof(float), 0);
    pairconv_p1_kernel<<<PG, T>>>(feats, w_p1, X0);                     // X0 = x

    reduce16_kernel<<<RG0, T>>>(X0, nullptr, nullptr, N0, 0, bn1g + 0, bn1b + 0, 1.0f / N0, 16);
    bnrelu_zero_kernel<<<gdiv(N0, T), T>>>(X0, T1, T2, N0, N0);
    pairconv16_kernel<27><<<PG, T>>>(RB0_P, 0, T1, w1 + 0 * 6912, T2);  // T2 = h1

    reduce16_kernel<<<RG0, T>>>(T2, nullptr, nullptr, N0, 0, bn2g + 0, bn2b + 0, 1.0f / N0, 16);
    bnrelu_zero_kernel<<<gdiv(N0, T), T>>>(T2, T1, nullptr, N0, 0);
    pairconv16_kernel<27><<<PG, T>>>(RB0_P, 0, T1, w2 + 0 * 6912, X0);  // X0 = r0

    reduce16_kernel<<<RG0, T>>>(X0, nullptr, nullptr, N0, 0, dbng + 0, dbnb + 0, 1.0f / N0, 16);
    bnrelu_zero_kernel<<<gdiv(N0, T), T>>>(X0, T1, X1, N0, N1);
    pairconv16_kernel<8><<<PG, T>>>(RB3_P, 96, T1, dw + 0 * 2048, X1);  // X1 = y1

    // ---- level 1 ----
    reduce16_kernel<<<RG1, T>>>(X1, nullptr, nullptr, N1, 0, bn1g + 16, bn1b + 16, 1.0f / N1, 16);
    bnrelu_zero_kernel<<<gdiv(N1, T), T>>>(X1, T1, T2, N1, N1);
    pairconv16_kernel<27><<<PG, T>>>(RB1_P, 32, T1, w1 + 1 * 6912, T2);

    reduce16_kernel<<<RG1, T>>>(T2, nullptr, nullptr, N1, 0, bn2g + 16, bn2b + 16, 1.0f / N1, 16);
    bnrelu_zero_kernel<<<gdiv(N1, T), T>>>(T2, T1, nullptr, N1, 0);
    pairconv16_kernel<27><<<PG, T>>>(RB1_P, 32, T1, w2 + 1 * 6912, X1); // X1 = r1

    reduce16_kernel<<<RG1, T>>>(X1, nullptr, nullptr, N1, 0, dbng + 16, dbnb + 16, 1.0f / N1, 16);
    bnrelu_zero_kernel<<<gdiv(N1, T), T>>>(X1, T1, X2, N1, N2);
    pairconv16_kernel<8><<<PG, T>>>(RB4_P, 128, T1, dw + 1 * 2048, X2); // X2 = z2

    // ---- level 2 ----
    reduce16_kernel<<<RG2, T>>>(X2, nullptr, nullptr, N2, 0, bn1g + 32, bn1b + 32, 1.0f / N2, 16);
    bnrelu_zero_kernel<<<gdiv(N2, T), T>>>(X2, T1, T2, N2, N2);
    pairconv16_kernel<27><<<PG, T>>>(RB2_P, 64, T1, w1 + 2 * 6912, T2);

    reduce16_kernel<<<RG2, T>>>(T2, nullptr, nullptr, N2, 0, bn2g + 32, bn2b + 32, 1.0f / N2, 16);
    bnrelu_zero_kernel<<<gdiv(N2, T), T>>>(T2, T1, nullptr, N2, 0);
    pairconv16_kernel<27><<<PG, T>>>(RB2_P, 64, T1, w2 + 2 * 6912, X2); // X2 = r2

    // ---- join + BN3 + SDF head ----
    reduce16_kernel<<<RG0, T>>>(X0, nullptr, nullptr, N0, 0,  nullptr, nullptr, 0.0f, 0);
    reduce16_kernel<<<RG0, T>>>(X1, p01, nullptr, N0, 16, nullptr, nullptr, 0.0f, 0);
    reduce16_kernel<<<RG0, T>>>(X2, p01, p12, N0, 32, bn3g, bn3b, 1.0f / N0, 48);

    final_out_kernel<<<gdiv(N0, T), T>>>(X0, X1, X2, p01, p12, wsdf, bsdf,
                                         (float*)d_out, N0);
}

// round 4
// speedup vs baseline: 1.2313x; 1.2313x over previous
#include <cuda_runtime.h>

#define N0MAX 500000
#define WMAX  15680          // >= gdiv(N0MAX, 32) + slack
#define EPS   1e-4f

// ---------------------------------------------------------------------------
// Scratch (device globals — no runtime allocation allowed)
// ---------------------------------------------------------------------------
__device__ float g_X0[N0MAX * 16];
__device__ float g_X1[N0MAX * 16];
__device__ float g_X2[N0MAX * 16];
__device__ float g_T1[N0MAX * 16];
__device__ float g_T2[N0MAX * 16];
// pair buffers: 3 rulebooks of K=27 + 2 of K=8, bucket stride N0MAX
__device__ int2     g_pairs[(size_t)97 * N0MAX];
__device__ int      g_wcnt[160 * WMAX];   // per-(bucket k, warp) counts -> bases
__device__ int      g_cnt[5 * 32];        // per-(bucket k) totals
__device__ float    g_stats[96];          // sum[0..47], sumsq[48..95]
__device__ float    g_scale[48];
__device__ float    g_shift[48];
__device__ unsigned g_ticket;

// rulebook bucket-base offsets into g_pairs / g_cnt
#define RB0_P ((size_t)0)
#define RB1_P ((size_t)27 * N0MAX)
#define RB2_P ((size_t)54 * N0MAX)
#define RB3_P ((size_t)81 * N0MAX)
#define RB4_P ((size_t)89 * N0MAX)

// ---------------------------------------------------------------------------
// f32x2 packed-math helpers (sm_103a FFMA2 — only reachable via PTX)
// ---------------------------------------------------------------------------
__device__ __forceinline__ unsigned long long fma2(unsigned long long a,
                                                   unsigned long long b,
                                                   unsigned long long c) {
    unsigned long long d;
    asm("fma.rn.f32x2 %0, %1, %2, %3;" : "=l"(d) : "l"(a), "l"(b), "l"(c));
    return d;
}
__device__ __forceinline__ unsigned long long dup2(float v) {
    unsigned long long d;
    asm("mov.b64 %0, {%1, %1};" : "=l"(d) : "f"(v));
    return d;
}
__device__ __forceinline__ float2 up2(unsigned long long v) {
    float2 f;
    asm("mov.b64 {%0, %1}, %2;" : "=f"(f.x), "=f"(f.y) : "l"(v));
    return f;
}
__device__ __forceinline__ void red4(float* p, float4 v) {
    asm volatile("red.global.add.v4.f32 [%0], {%1, %2, %3, %4};"
                 :: "l"(p), "f"(v.x), "f"(v.y), "f"(v.z), "f"(v.w) : "memory");
}

// ---------------------------------------------------------------------------
// Zero stats + ticket (start of every call)
// ---------------------------------------------------------------------------
__global__ void zero_misc_kernel() {
    int t = threadIdx.x;
    if (t < 96) g_stats[t] = 0.0f;
    if (t == 0) g_ticket = 0u;
}

// ---------------------------------------------------------------------------
// Compaction phase 1: per-(k, warp) active counts. Plain stores, no atomics.
// ---------------------------------------------------------------------------
template <int K>
__global__ void count_kernel(const int* __restrict__ nbr, int Nout, int Nin,
                             int cbase) {
    int i = blockIdx.x * blockDim.x + threadIdx.x;
    bool inb = i < Nout;
    int lane = threadIdx.x & 31;
    int w = i >> 5;
#pragma unroll 1
    for (int k = 0; k < K; k++) {
        int idx = inb ? __ldg(nbr + (size_t)k * Nout + i) : Nin;
        unsigned m = __ballot_sync(0xffffffffu, idx < Nin);
        if (lane == 0) g_wcnt[(size_t)(cbase + k) * WMAX + w] = __popc(m);
    }
}

// ---------------------------------------------------------------------------
// Compaction phase 2: exclusive prefix over warp counts, one block per k-row.
// shfl warp-scan + cross-warp offsets; writes row total to g_cnt.
// ---------------------------------------------------------------------------
__global__ void scan_rows_kernel(int cbase, int nw) {
    int row = cbase + blockIdx.x;
    int* p = g_wcnt + (size_t)row * WMAX;
    int t = threadIdx.x, lane = t & 31, wid = t >> 5;
    __shared__ int wtot[8];
    __shared__ int carry;
    if (t == 0) carry = 0;
    __syncthreads();
    for (int base = 0; base < nw; base += 256) {
        int v = (base + t < nw) ? p[base + t] : 0;
        int x = v;
#pragma unroll
        for (int off = 1; off < 32; off <<= 1) {
            int y = __shfl_up_sync(0xffffffffu, x, off);
            if (lane >= off) x += y;
        }
        if (lane == 31) wtot[wid] = x;
        __syncthreads();
        int wofs = 0;
#pragma unroll
        for (int w2 = 0; w2 < 8; w2++) wofs += (w2 < wid) ? wtot[w2] : 0;
        int excl = x - v + wofs + carry;
        if (base + t < nw) p[base + t] = excl;
        __syncthreads();
        if (t == 0) {
            int s = 0;
#pragma unroll
            for (int w2 = 0; w2 < 8; w2++) s += wtot[w2];
            carry += s;
        }
        __syncthreads();
    }
    if (t == 0) g_cnt[row] = carry;
}

// ---------------------------------------------------------------------------
// Compaction phase 3: write pairs at deterministic slots. No atomics/syncs.
// ---------------------------------------------------------------------------
template <int K>
__global__ void fill_kernel(const int* __restrict__ nbr, int Nout, int Nin,
                            int cbase, size_t pbase) {
    int i = blockIdx.x * blockDim.x + threadIdx.x;
    bool inb = i < Nout;
    int lane = threadIdx.x & 31;
    int w = i >> 5;
    unsigned lt = (1u << lane) - 1u;
#pragma unroll 1
    for (int k = 0; k < K; k++) {
        int idx = inb ? __ldg(nbr + (size_t)k * Nout + i) : Nin;
        bool act = idx < Nin;
        unsigned m = __ballot_sync(0xffffffffu, act);
        if (!m) continue;
        int base = __ldg(&g_wcnt[(size_t)(cbase + k) * WMAX + w]);
        if (act)
            g_pairs[pbase + (size_t)k * N0MAX + base + __popc(m & lt)] =
                make_int2(i, idx);
    }
}

// ---------------------------------------------------------------------------
// Pair-parallel sparse conv, 16->16, f32x2 packed math.
// One thread = one (out_i, in_idx, k) pair; k warp-uniform (k-major buckets)
// -> broadcast LDS.128 weight reads. Accumulate via red.global.add.v4.f32.
// ---------------------------------------------------------------------------
template <int K>
__global__ void pairconv16_kernel(size_t pbase, int cbase,
                                  const float* __restrict__ y,
                                  const float* __restrict__ Wg,  // [K,16,16]
                                  float* __restrict__ out) {
    __shared__ float4 Ws[K * 64];
    __shared__ int spfx[K + 1];
    for (int t = threadIdx.x; t < K * 64; t += blockDim.x)
        Ws[t] = __ldg((const float4*)Wg + t);
    if (threadIdx.x == 0) {
        int s = 0;
        for (int k = 0; k < K; k++) { spfx[k] = s; s += g_cnt[cbase + k]; }
        spfx[K] = s;
    }
    __syncthreads();
    int P = spfx[K];

    for (int t = blockIdx.x * blockDim.x + threadIdx.x; t < P;
         t += gridDim.x * blockDim.x) {
        int lo = 0, hi = K;
        while (hi - lo > 1) {
            int mid = (lo + hi) >> 1;
            if (spfx[mid] <= t) lo = mid; else hi = mid;
        }
        int2 pr = __ldg(&g_pairs[pbase + (size_t)lo * N0MAX + (t - spfx[lo])]);
        const float4* yr = (const float4*)(y + (size_t)pr.y * 16);
        float4 y0 = __ldg(yr + 0), y1 = __ldg(yr + 1);
        float4 y2 = __ldg(yr + 2), y3 = __ldg(yr + 3);
        const ulonglong2* Wk = (const ulonglong2*)(Ws + (size_t)lo * 64);
        unsigned long long a0 = 0, a1 = 0, a2 = 0, a3 = 0,
                           a4 = 0, a5 = 0, a6 = 0, a7 = 0;

#define JSTEP(jj, yv) { \
        unsigned long long yy = dup2(yv); \
        ulonglong2 p0 = Wk[4*(jj)+0], p1 = Wk[4*(jj)+1]; \
        ulonglong2 p2 = Wk[4*(jj)+2], p3 = Wk[4*(jj)+3]; \
        a0 = fma2(yy, p0.x, a0); a1 = fma2(yy, p0.y, a1); \
        a2 = fma2(yy, p1.x, a2); a3 = fma2(yy, p1.y, a3); \
        a4 = fma2(yy, p2.x, a4); a5 = fma2(yy, p2.y, a5); \
        a6 = fma2(yy, p3.x, a6); a7 = fma2(yy, p3.y, a7); }

        JSTEP(0, y0.x)  JSTEP(1, y0.y)  JSTEP(2, y0.z)  JSTEP(3, y0.w)
        JSTEP(4, y1.x)  JSTEP(5, y1.y)  JSTEP(6, y1.z)  JSTEP(7, y1.w)
        JSTEP(8, y2.x)  JSTEP(9, y2.y)  JSTEP(10, y2.z) JSTEP(11, y2.w)
        JSTEP(12, y3.x) JSTEP(13, y3.y) JSTEP(14, y3.z) JSTEP(15, y3.w)
#undef JSTEP

        float* op = out + (size_t)pr.x * 16;
        float2 f0 = up2(a0), f1 = up2(a1), f2 = up2(a2), f3 = up2(a3);
        float2 f4 = up2(a4), f5 = up2(a5), f6 = up2(a6), f7 = up2(a7);
        red4(op + 0,  make_float4(f0.x, f0.y, f1.x, f1.y));
        red4(op + 4,  make_float4(f2.x, f2.y, f3.x, f3.y));
        red4(op + 8,  make_float4(f4.x, f4.y, f5.x, f5.y));
        red4(op + 12, make_float4(f6.x, f6.y, f7.x, f7.y));
    }
}

// p1 pair conv: Cin=2 -> 16, K=27, input = raw feats (no BN)
__global__ void pairconv_p1_kernel(const float* __restrict__ feats,
                                   const float* __restrict__ Wg,  // [27,2,16]
                                   float* __restrict__ out) {
    __shared__ float4 Ws[27 * 8];
    __shared__ int spfx[28];
    for (int t = threadIdx.x; t < 27 * 8; t += blockDim.x)
        Ws[t] = __ldg((const float4*)Wg + t);
    if (threadIdx.x == 0) {
        int s = 0;
        for (int k = 0; k < 27; k++) { spfx[k] = s; s += g_cnt[k]; }
        spfx[27] = s;
    }
    __syncthreads();
    int P = spfx[27];

    for (int t = blockIdx.x * blockDim.x + threadIdx.x; t < P;
         t += gridDim.x * blockDim.x) {
        int lo = 0, hi = 27;
        while (hi - lo > 1) {
            int mid = (lo + hi) >> 1;
            if (spfx[mid] <= t) lo = mid; else hi = mid;
        }
        int2 pr = __ldg(&g_pairs[RB0_P + (size_t)lo * N0MAX + (t - spfx[lo])]);
        float2 f = __ldg((const float2*)(feats + (size_t)pr.y * 2));
        const float4* Wk = &Ws[lo * 8];
        float4 u0 = Wk[0], u1 = Wk[1], u2 = Wk[2], u3 = Wk[3];
        float4 v0 = Wk[4], v1 = Wk[5], v2 = Wk[6], v3 = Wk[7];
        float4 a0 = make_float4(fmaf(f.y, v0.x, f.x * u0.x), fmaf(f.y, v0.y, f.x * u0.y),
                                fmaf(f.y, v0.z, f.x * u0.z), fmaf(f.y, v0.w, f.x * u0.w));
        float4 a1 = make_float4(fmaf(f.y, v1.x, f.x * u1.x), fmaf(f.y, v1.y, f.x * u1.y),
                                fmaf(f.y, v1.z, f.x * u1.z), fmaf(f.y, v1.w, f.x * u1.w));
        float4 a2 = make_float4(fmaf(f.y, v2.x, f.x * u2.x), fmaf(f.y, v2.y, f.x * u2.y),
                                fmaf(f.y, v2.z, f.x * u2.z), fmaf(f.y, v2.w, f.x * u2.w));
        float4 a3 = make_float4(fmaf(f.y, v3.x, f.x * u3.x), fmaf(f.y, v3.y, f.x * u3.y),
                                fmaf(f.y, v3.z, f.x * u3.z), fmaf(f.y, v3.w, f.x * u3.w));
        float* op = out + (size_t)pr.x * 16;
        red4(op + 0, a0); red4(op + 4, a1); red4(op + 8, a2); red4(op + 12, a3);
    }
}

// ---------------------------------------------------------------------------
// y = relu(x*scale+shift); optionally zero-init zb[Nz rows] in the same pass.
// ---------------------------------------------------------------------------
__global__ void bnrelu_zero_kernel(const float* __restrict__ x,
                                   float* __restrict__ y,
                                   float* __restrict__ zb, int N, int Nz) {
    int i = blockIdx.x * blockDim.x + threadIdx.x;
    if (i < N) {
        const float4* xr = (const float4*)(x + (size_t)i * 16);
        float4* yr = (float4*)(y + (size_t)i * 16);
#pragma unroll
        for (int q = 0; q < 4; q++) {
            float4 v = __ldg(xr + q);
            v.x = fmaxf(fmaf(v.x, g_scale[4 * q + 0], g_shift[4 * q + 0]), 0.f);
            v.y = fmaxf(fmaf(v.y, g_scale[4 * q + 1], g_shift[4 * q + 1]), 0.f);
            v.z = fmaxf(fmaf(v.z, g_scale[4 * q + 2], g_shift[4 * q + 2]), 0.f);
            v.w = fmaxf(fmaf(v.w, g_scale[4 * q + 3], g_shift[4 * q + 3]), 0.f);
            yr[q] = v;
        }
    }
    if (zb != nullptr && i < Nz) {
        float4* zr = (float4*)(zb + (size_t)i * 16);
        float4 z = make_float4(0.f, 0.f, 0.f, 0.f);
        zr[0] = z; zr[1] = z; zr[2] = z; zr[3] = z;
    }
}

// ---------------------------------------------------------------------------
// Per-channel sum / sumsq over N rows (optional gather row=pB[pA[i]]), with
// BN finalize fused into the last-arriving block (Cfin>0).
// ---------------------------------------------------------------------------
__global__ void reduce16_kernel(const float* __restrict__ x,
                                const int* __restrict__ pA,
                                const int* __restrict__ pB,
                                int N, int off,
                                const float* __restrict__ gg,
                                const float* __restrict__ bb,
                                float invN, int Cfin) {
    float s[16], q[16];
#pragma unroll
    for (int c = 0; c < 16; c++) { s[c] = 0.0f; q[c] = 0.0f; }

    for (int i = blockIdx.x * blockDim.x + threadIdx.x; i < N;
         i += gridDim.x * blockDim.x) {
        int r = i;
        if (pA) r = __ldg(pA + r);
        if (pB) r = __ldg(pB + r);
        const float4* xr = (const float4*)(x + (size_t)r * 16);
#pragma unroll
        for (int t = 0; t < 4; t++) {
            float4 v = __ldg(xr + t);
            s[4 * t + 0] += v.x; q[4 * t + 0] += v.x * v.x;
            s[4 * t + 1] += v.y; q[4 * t + 1] += v.y * v.y;
            s[4 * t + 2] += v.z; q[4 * t + 2] += v.z * v.z;
            s[4 * t + 3] += v.w; q[4 * t + 3] += v.w * v.w;
        }
    }
#pragma unroll
    for (int c = 0; c < 16; c++) {
#pragma unroll
        for (int o = 16; o > 0; o >>= 1) {
            s[c] += __shfl_xor_sync(0xffffffffu, s[c], o);
            q[c] += __shfl_xor_sync(0xffffffffu, q[c], o);
        }
    }
    __shared__ float ws[8][32];
    __shared__ bool last;
    int lane = threadIdx.x & 31, wid = threadIdx.x >> 5;
    if (lane == 0) {
#pragma unroll
        for (int c = 0; c < 16; c++) { ws[wid][c] = s[c]; ws[wid][16 + c] = q[c]; }
    }
    __syncthreads();
    if (threadIdx.x < 32) {
        float v = 0.0f;
        int nw = blockDim.x >> 5;
        for (int w = 0; w < nw; w++) v += ws[w][threadIdx.x];
        int t = threadIdx.x;
        int gi = (t < 16) ? (off + t) : (48 + off + (t - 16));
        atomicAdd(&g_stats[gi], v);
    }
    if (Cfin == 0) return;
    __threadfence();
    if (threadIdx.x == 0) {
        unsigned tk = atomicAdd(&g_ticket, 1u);
        last = (tk == (unsigned)gridDim.x - 1u);
    }
    __syncthreads();
    if (!last) return;
    if (threadIdx.x == 0) g_ticket = 0u;
    int t = threadIdx.x;
    if (t < Cfin) {
        float sm = __ldcg(&g_stats[t]);
        float sq = __ldcg(&g_stats[48 + t]);
        float m = sm * invN;
        float var = sq * invN - m * m;
        float sc = __ldg(gg + t) * rsqrtf(var + EPS);
        g_scale[t] = sc;
        g_shift[t] = __ldg(bb + t) - m * sc;
        g_stats[t] = 0.0f;
        g_stats[48 + t] = 0.0f;
    }
}

// ---------------------------------------------------------------------------
// Final: fused unpool-join (3x16 gather) + BN3-ReLU + SDF linear head.
// ---------------------------------------------------------------------------
__global__ void final_out_kernel(const float* __restrict__ x0,
                                 const float* __restrict__ x1,
                                 const float* __restrict__ x2,
                                 const int* __restrict__ p01,
                                 const int* __restrict__ p12,
                                 const float* __restrict__ wsdf,
                                 const float* __restrict__ bsdf,
                                 float* __restrict__ out, int N0) {
    __shared__ float sw[48], ssc[48], ssh[48];
    if (threadIdx.x < 48) {
        sw[threadIdx.x] = __ldg(wsdf + threadIdx.x);
        ssc[threadIdx.x] = g_scale[threadIdx.x];
        ssh[threadIdx.x] = g_shift[threadIdx.x];
    }
    __syncthreads();
    int i = blockIdx.x * blockDim.x + threadIdx.x;
    if (i >= N0) return;
    int p = __ldg(p01 + i);
    int qq = __ldg(p12 + p);
    float r = __ldg(bsdf);
    const float* rows[3] = { x0 + (size_t)i * 16, x1 + (size_t)p * 16,
                             x2 + (size_t)qq * 16 };
#pragma unroll
    for (int gidx = 0; gidx < 3; gidx++) {
        const float4* xr = (const float4*)rows[gidx];
#pragma unroll
        for (int t = 0; t < 4; t++) {
            float4 v = __ldg(xr + t);
            int c = gidx * 16 + t * 4;
            r += fmaxf(fmaf(v.x, ssc[c + 0], ssh[c + 0]), 0.0f) * sw[c + 0];
            r += fmaxf(fmaf(v.y, ssc[c + 1], ssh[c + 1]), 0.0f) * sw[c + 1];
            r += fmaxf(fmaf(v.z, ssc[c + 2], ssh[c + 2]), 0.0f) * sw[c + 2];
            r += fmaxf(fmaf(v.w, ssc[c + 3], ssh[c + 3]), 0.0f) * sw[c + 3];
        }
    }
    out[i] = r;
}

// ---------------------------------------------------------------------------
// Host orchestration
// ---------------------------------------------------------------------------
static inline int gdiv(int n, int t) { return (n + t - 1) / t; }

extern "C" void kernel_launch(void* const* d_in, const int* in_sizes, int n_in,
                              void* d_out, int out_size) {
    const float* feats = (const float*)d_in[0];
    const float* w_p1  = (const float*)d_in[1];
    const float* bn1g  = (const float*)d_in[2];
    const float* bn1b  = (const float*)d_in[3];
    const float* w1    = (const float*)d_in[4];
    const float* bn2g  = (const float*)d_in[5];
    const float* bn2b  = (const float*)d_in[6];
    const float* w2    = (const float*)d_in[7];
    const float* dbng  = (const float*)d_in[8];
    const float* dbnb  = (const float*)d_in[9];
    const float* dw    = (const float*)d_in[10];
    const float* bn3g  = (const float*)d_in[11];
    const float* bn3b  = (const float*)d_in[12];
    const float* wsdf  = (const float*)d_in[13];
    const float* bsdf  = (const float*)d_in[14];
    const int* nbr0    = (const int*)d_in[15];
    const int* nbr1    = (const int*)d_in[16];
    const int* nbr2    = (const int*)d_in[17];
    const int* down01  = (const int*)d_in[18];
    const int* down12  = (const int*)d_in[19];
    const int* p01     = (const int*)d_in[20];
    const int* p12     = (const int*)d_in[21];

    int N0 = in_sizes[0] / 2;
    int N1 = in_sizes[16] / 27;
    int N2 = in_sizes[17] / 27;

    float *X0, *X1, *X2, *T1, *T2;
    cudaGetSymbolAddress((void**)&X0, g_X0);
    cudaGetSymbolAddress((void**)&X1, g_X1);
    cudaGetSymbolAddress((void**)&X2, g_X2);
    cudaGetSymbolAddress((void**)&T1, g_T1);
    cudaGetSymbolAddress((void**)&T2, g_T2);

    const int T = 256;
    const int PG = 1184;   // grid-stride grid for pair convs
    const int RG0 = (gdiv(N0, T) < 1184) ? gdiv(N0, T) : 1184;
    const int RG1 = (gdiv(N1, T) < 1184) ? gdiv(N1, T) : 1184;
    const int RG2 = (gdiv(N2, T) < 1184) ? gdiv(N2, T) : 1184;

    // ---- compaction of all 5 rulebooks (count -> scan -> fill, atomic-free) ----
    zero_misc_kernel<<<1, 128>>>();
    count_kernel<27><<<gdiv(N0, T), T>>>(nbr0, N0, N0, 0);
    count_kernel<27><<<gdiv(N1, T), T>>>(nbr1, N1, N1, 32);
    count_kernel<27><<<gdiv(N2, T), T>>>(nbr2, N2, N2, 64);
    count_kernel<8> <<<gdiv(N1, T), T>>>(down01, N1, N0, 96);
    count_kernel<8> <<<gdiv(N2, T), T>>>(down12, N2, N1, 128);
    scan_rows_kernel<<<27, 256>>>(0,   gdiv(N0, 32));
    scan_rows_kernel<<<27, 256>>>(32,  gdiv(N1, 32));
    scan_rows_kernel<<<27, 256>>>(64,  gdiv(N2, 32));
    scan_rows_kernel<<<8,  256>>>(96,  gdiv(N1, 32));
    scan_rows_kernel<<<8,  256>>>(128, gdiv(N2, 32));
    fill_kernel<27><<<gdiv(N0, T), T>>>(nbr0, N0, N0, 0,    RB0_P);
    fill_kernel<27><<<gdiv(N1, T), T>>>(nbr1, N1, N1, 32,   RB1_P);
    fill_kernel<27><<<gdiv(N2, T), T>>>(nbr2, N2, N2, 64,   RB2_P);
    fill_kernel<8> <<<gdiv(N1, T), T>>>(down01, N1, N0, 96,  RB3_P);
    fill_kernel<8> <<<gdiv(N2, T), T>>>(down12, N2, N1, 128, RB4_P);

    // ---- level 0 ----
    cudaMemsetAsync(X0, 0, (size_t)N0 * 16 * sizeof(float), 0);
    pairconv_p1_kernel<<<PG, T>>>(feats, w_p1, X0);                     // X0 = x

    reduce16_kernel<<<RG0, T>>>(X0, nullptr, nullptr, N0, 0, bn1g + 0, bn1b + 0, 1.0f / N0, 16);
    bnrelu_zero_kernel<<<gdiv(N0, T), T>>>(X0, T1, T2, N0, N0);
    pairconv16_kernel<27><<<PG, T>>>(RB0_P, 0, T1, w1 + 0 * 6912, T2);  // T2 = h1

    reduce16_kernel<<<RG0, T>>>(T2, nullptr, nullptr, N0, 0, bn2g + 0, bn2b + 0, 1.0f / N0, 16);
    bnrelu_zero_kernel<<<gdiv(N0, T), T>>>(T2, T1, nullptr, N0, 0);
    pairconv16_kernel<27><<<PG, T>>>(RB0_P, 0, T1, w2 + 0 * 6912, X0);  // X0 = r0

    reduce16_kernel<<<RG0, T>>>(X0, nullptr, nullptr, N0, 0, dbng + 0, dbnb + 0, 1.0f / N0, 16);
    bnrelu_zero_kernel<<<gdiv(N0, T), T>>>(X0, T1, X1, N0, N1);
    pairconv16_kernel<8><<<PG, T>>>(RB3_P, 96, T1, dw + 0 * 2048, X1);  // X1 = y1

    // ---- level 1 ----
    reduce16_kernel<<<RG1, T>>>(X1, nullptr, nullptr, N1, 0, bn1g + 16, bn1b + 16, 1.0f / N1, 16);
    bnrelu_zero_kernel<<<gdiv(N1, T), T>>>(X1, T1, T2, N1, N1);
    pairconv16_kernel<27><<<PG, T>>>(RB1_P, 32, T1, w1 + 1 * 6912, T2);

    reduce16_kernel<<<RG1, T>>>(T2, nullptr, nullptr, N1, 0, bn2g + 16, bn2b + 16, 1.0f / N1, 16);
    bnrelu_zero_kernel<<<gdiv(N1, T), T>>>(T2, T1, nullptr, N1, 0);
    pairconv16_kernel<27><<<PG, T>>>(RB1_P, 32, T1, w2 + 1 * 6912, X1); // X1 = r1

    reduce16_kernel<<<RG1, T>>>(X1, nullptr, nullptr, N1, 0, dbng + 16, dbnb + 16, 1.0f / N1, 16);
    bnrelu_zero_kernel<<<gdiv(N1, T), T>>>(X1, T1, X2, N1, N2);
    pairconv16_kernel<8><<<PG, T>>>(RB4_P, 128, T1, dw + 1 * 2048, X2); // X2 = z2

    // ---- level 2 ----
    reduce16_kernel<<<RG2, T>>>(X2, nullptr, nullptr, N2, 0, bn1g + 32, bn1b + 32, 1.0f / N2, 16);
    bnrelu_zero_kernel<<<gdiv(N2, T), T>>>(X2, T1, T2, N2, N2);
    pairconv16_kernel<27><<<PG, T>>>(RB2_P, 64, T1, w1 + 2 * 6912, T2);

    reduce16_kernel<<<RG2, T>>>(T2, nullptr, nullptr, N2, 0, bn2g + 32, bn2b + 32, 1.0f / N2, 16);
    bnrelu_zero_kernel<<<gdiv(N2, T), T>>>(T2, T1, nullptr, N2, 0);
    pairconv16_kernel<27><<<PG, T>>>(RB2_P, 64, T1, w2 + 2 * 6912, X2); // X2 = r2

    // ---- join + BN3 + SDF head ----
    reduce16_kernel<<<RG0, T>>>(X0, nullptr, nullptr, N0, 0,  nullptr, nullptr, 0.0f, 0);
    reduce16_kernel<<<RG0, T>>>(X1, p01, nullptr, N0, 16, nullptr, nullptr, 0.0f, 0);
    reduce16_kernel<<<RG0, T>>>(X2, p01, p12, N0, 32, bn3g, bn3b, 1.0f / N0, 48);

    final_out_kernel<<<gdiv(N0, T), T>>>(X0, X1, X2, p01, p12, wsdf, bsdf,
                                         (float*)d_out, N0);
}